// round 5
// baseline (speedup 1.0000x reference)
#include <cuda_runtime.h>
#include <math.h>

#define NMAX 65536
#define HD   128

typedef unsigned long long u64;

// Scratch (device globals: no allocation allowed in kernel_launch)
__device__ float g_agg1[NMAX * 32];
__device__ float g_h   [NMAX * HD];
__device__ float g_agg2[NMAX * HD];   // reused as nh2 buffer at the end
__device__ float g_h2  [NMAX * HD];
__device__ float g_t1  [NMAX * HD];
__device__ float g_pooled[64 * HD];

__device__ __forceinline__ float leakyf(float v) { return v > 0.f ? v : 0.01f * v; }

__device__ __forceinline__ u64 pack2(float lo, float hi) {
    u64 r; asm("mov.b64 %0, {%1, %2};" : "=l"(r) : "f"(lo), "f"(hi)); return r;
}
__device__ __forceinline__ void unpack2(float& lo, float& hi, u64 v) {
    asm("mov.b64 {%0, %1}, %2;" : "=f"(lo), "=f"(hi) : "l"(v));
}
__device__ __forceinline__ u64 fma2(u64 a, u64 b, u64 c) {
    u64 d; asm("fma.rn.f32x2 %0, %1, %2, %3;" : "=l"(d) : "l"(a), "l"(b), "l"(c)); return d;
}

// ---------------------------------------------------------------------------
// Edge layer 1: msg = relu(x[src] + ea @ e1_w + b); red-add into agg1 [N,32]
// One warp / 32 edges; lane owns 1 of 32 channels. W in regs, split-chain ILP,
// next-edge loads prefetched.
// ---------------------------------------------------------------------------
#define E1_CHUNK 32
__global__ __launch_bounds__(256)
void edge1_kernel(const float* __restrict__ x, const int* __restrict__ src,
                  const int* __restrict__ dst, const float* __restrict__ ea,
                  const float* __restrict__ W, const float* __restrict__ bias,
                  float* __restrict__ agg, int E)
{
    int lane = threadIdx.x & 31;
    int warp = blockIdx.x * 8 + (threadIdx.x >> 5);
    int base = warp * E1_CHUNK;
    if (base >= E) return;

    float w[16];
    #pragma unroll
    for (int k = 0; k < 16; k++) w[k] = __ldg(&W[k * 32 + lane]);
    float b = __ldg(&bias[lane]);

    int sA = __ldg(&src[base + lane]);
    int sD = __ldg(&dst[base + lane]);

    // prefetch edge 0
    int s0 = __shfl_sync(0xffffffffu, sA, 0);
    float av = (lane < 16) ? __ldg(&ea[(size_t)base * 16 + lane]) : 0.f;
    float g  = __ldg(&x[(size_t)s0 * 32 + lane]);

    #pragma unroll 4
    for (int i = 0; i < E1_CHUNK; i++) {
        float av_n = 0.f, g_n = 0.f;
        if (i + 1 < E1_CHUNK) {
            int s1 = __shfl_sync(0xffffffffu, sA, i + 1);
            av_n = (lane < 16) ? __ldg(&ea[(size_t)(base + i + 1) * 16 + lane]) : 0.f;
            g_n  = __ldg(&x[(size_t)s1 * 32 + lane]);
        }
        int d = __shfl_sync(0xffffffffu, sD, i);
        float t0 = b, t1 = 0.f;
        #pragma unroll
        for (int k = 0; k < 16; k += 2) {
            t0 = fmaf(__shfl_sync(0xffffffffu, av, k),     w[k],     t0);
            t1 = fmaf(__shfl_sync(0xffffffffu, av, k + 1), w[k + 1], t1);
        }
        float m = fmaxf(t0 + t1 + g, 0.f);
        asm volatile("red.global.add.f32 [%0], %1;"
                     :: "l"(agg + (size_t)d * 32 + lane), "f"(m) : "memory");
        av = av_n; g = g_n;
    }
}

// ---------------------------------------------------------------------------
// Edge layer 2: msg = relu(h[src] + ea @ e2_w + b); red-add into agg2 [N,128]
// One warp / 16 edges; lane owns 4 of 128 channels. W in regs (f32x2),
// 2-way split accumulator chains + next-edge prefetch.
// ---------------------------------------------------------------------------
#define E2_CHUNK 16
__global__ __launch_bounds__(256)
void edge2_kernel(const float* __restrict__ h, const int* __restrict__ src,
                  const int* __restrict__ dst, const float* __restrict__ ea,
                  const float* __restrict__ W, const float* __restrict__ bias,
                  float* __restrict__ agg, int E)
{
    int lane = threadIdx.x & 31;
    int warp = blockIdx.x * 8 + (threadIdx.x >> 5);
    int base = warp * E2_CHUNK;
    if (base >= E) return;

    u64 w01[16], w23[16];
    #pragma unroll
    for (int k = 0; k < 16; k++) {
        float4 wv = *(const float4*)(W + (size_t)k * 128 + lane * 4);
        w01[k] = pack2(wv.x, wv.y);
        w23[k] = pack2(wv.z, wv.w);
    }
    float4 b4 = ((const float4*)bias)[lane];
    u64 b01 = pack2(b4.x, b4.y), b23 = pack2(b4.z, b4.w);

    int li = lane & 15;
    int sd = (lane < 16) ? __ldg(&src[base + li]) : __ldg(&dst[base + li]);

    // prefetch edge 0
    int s0 = __shfl_sync(0xffffffffu, sd, 0);
    float av = (lane < 16) ? __ldg(&ea[(size_t)base * 16 + lane]) : 0.f;
    float4 g = *(const float4*)(h + (size_t)s0 * HD + lane * 4);

    #pragma unroll 2
    for (int i = 0; i < E2_CHUNK; i++) {
        float av_n = 0.f;
        float4 g_n = make_float4(0.f, 0.f, 0.f, 0.f);
        if (i + 1 < E2_CHUNK) {
            int s1 = __shfl_sync(0xffffffffu, sd, i + 1);
            av_n = (lane < 16) ? __ldg(&ea[(size_t)(base + i + 1) * 16 + lane]) : 0.f;
            g_n = *(const float4*)(h + (size_t)s1 * HD + lane * 4);
        }
        int d = __shfl_sync(0xffffffffu, sd, 16 + i);

        // 4 independent fma2 chains (even-k / odd-k per half)
        u64 tA = b01, tB = 0ull, tC = b23, tD = 0ull;
        #pragma unroll
        for (int k = 0; k < 16; k += 2) {
            float a0 = __shfl_sync(0xffffffffu, av, k);
            float a1 = __shfl_sync(0xffffffffu, av, k + 1);
            u64 aa0 = pack2(a0, a0);
            u64 aa1 = pack2(a1, a1);
            tA = fma2(aa0, w01[k],     tA);
            tC = fma2(aa0, w23[k],     tC);
            tB = fma2(aa1, w01[k + 1], tB);
            tD = fma2(aa1, w23[k + 1], tD);
        }
        float tx, ty, tz, tw, ux, uy, uz, uw;
        unpack2(tx, ty, tA); unpack2(ux, uy, tB);
        unpack2(tz, tw, tC); unpack2(uz, uw, tD);
        float mx = fmaxf(tx + ux + g.x, 0.f);
        float my = fmaxf(ty + uy + g.y, 0.f);
        float mz = fmaxf(tz + uz + g.z, 0.f);
        float mw = fmaxf(tw + uw + g.w, 0.f);
        asm volatile("red.global.add.v4.f32 [%0], {%1,%2,%3,%4};"
                     :: "l"(agg + (size_t)d * HD + lane * 4),
                        "f"(mx), "f"(my), "f"(mz), "f"(mw) : "memory");
        av = av_n; g = g_n;
    }
}

// ---------------------------------------------------------------------------
// GEMM: Out[N,128] = act( (In (+In2)) @ W[K,128] + bias ), f32x2 packed FMA.
// 256 threads/block, 64x128 tile, per-thread 8 rows x 4 cols.
// ACT: 0 = leaky_relu(0.01), 1 = relu
// ---------------------------------------------------------------------------
template<int K, int ACT, bool ADD>
__global__ __launch_bounds__(256)
void gemm_kernel(const float* __restrict__ In, const float* __restrict__ In2,
                 const float* __restrict__ W, const float* __restrict__ bias,
                 float* __restrict__ Out)
{
    __shared__ float sIn[64 * K];
    __shared__ float sW[16 * 128];
    int tid = threadIdx.x;
    int row0 = blockIdx.x * 64;

    const float4* inp  = (const float4*)(In  + (size_t)row0 * K);
    const float4* inp2 = (const float4*)(In2 + (size_t)row0 * K);
    for (int i = tid; i < (64 * K) / 4; i += 256) {
        float4 v = inp[i];
        if (ADD) {
            float4 u = inp2[i];
            v.x += u.x; v.y += u.y; v.z += u.z; v.w += u.w;
        }
        ((float4*)sIn)[i] = v;
    }

    int cx = tid & 31;
    int ry = tid >> 5;
    float4 b4 = ((const float4*)bias)[cx];
    u64 acc01[8], acc23[8];
    #pragma unroll
    for (int m = 0; m < 8; m++) { acc01[m] = pack2(b4.x, b4.y); acc23[m] = pack2(b4.z, b4.w); }

    for (int kc = 0; kc < K; kc += 16) {
        __syncthreads();
        for (int i = tid; i < (16 * 128) / 4; i += 256)
            ((float4*)sW)[i] = ((const float4*)(W + (size_t)kc * 128))[i];
        __syncthreads();
        #pragma unroll
        for (int k4 = 0; k4 < 16; k4 += 4) {
            u64 w01[4], w23[4];
            #pragma unroll
            for (int j = 0; j < 4; j++) {
                float4 wv = ((float4*)sW)[(k4 + j) * 32 + cx];
                w01[j] = pack2(wv.x, wv.y);
                w23[j] = pack2(wv.z, wv.w);
            }
            #pragma unroll
            for (int m = 0; m < 8; m++) {
                float4 a4 = *(const float4*)&sIn[(ry * 8 + m) * K + kc + k4];
                u64 aa;
                aa = pack2(a4.x, a4.x); acc01[m] = fma2(aa, w01[0], acc01[m]); acc23[m] = fma2(aa, w23[0], acc23[m]);
                aa = pack2(a4.y, a4.y); acc01[m] = fma2(aa, w01[1], acc01[m]); acc23[m] = fma2(aa, w23[1], acc23[m]);
                aa = pack2(a4.z, a4.z); acc01[m] = fma2(aa, w01[2], acc01[m]); acc23[m] = fma2(aa, w23[2], acc23[m]);
                aa = pack2(a4.w, a4.w); acc01[m] = fma2(aa, w01[3], acc01[m]); acc23[m] = fma2(aa, w23[3], acc23[m]);
            }
        }
    }

    #pragma unroll
    for (int m = 0; m < 8; m++) {
        float4 v;
        unpack2(v.x, v.y, acc01[m]);
        unpack2(v.z, v.w, acc23[m]);
        if (ACT == 0) {
            v.x = leakyf(v.x); v.y = leakyf(v.y); v.z = leakyf(v.z); v.w = leakyf(v.w);
        } else {
            v.x = fmaxf(v.x, 0.f); v.y = fmaxf(v.y, 0.f);
            v.z = fmaxf(v.z, 0.f); v.w = fmaxf(v.w, 0.f);
        }
        *(float4*)(Out + (size_t)(row0 + ry * 8 + m) * 128 + cx * 4) = v;
    }
}

// ---------------------------------------------------------------------------
// Graph mean pooling: pooled[b][c] = mean_i h2[b*Nper+i][c]
// ---------------------------------------------------------------------------
__global__ void pool_kernel(const float* __restrict__ h2, float* __restrict__ pooled, int Nper)
{
    int b = blockIdx.x;
    int tid = threadIdx.x;
    int c = tid & 127, half = tid >> 7;
    float s = 0.f;
    const float* base = h2 + (size_t)b * Nper * HD + c;
    for (int i = half; i < Nper; i += 2) s += base[(size_t)i * HD];
    __shared__ float sm[256];
    sm[tid] = s;
    __syncthreads();
    if (half == 0) pooled[b * HD + c] = (sm[c] + sm[128 + c]) / (float)Nper;
}

// ---------------------------------------------------------------------------
// Action head: softmax(leaky(leaky(pooled@a_w1+b1)@a_w2+b2))
// ---------------------------------------------------------------------------
__global__ void action_kernel(const float* __restrict__ pooled,
                              const float* __restrict__ w1, const float* __restrict__ b1,
                              const float* __restrict__ w2, const float* __restrict__ b2,
                              float* __restrict__ out)
{
    __shared__ float sp[128], s1[128], s2[10];
    int b = blockIdx.x;
    int tid = threadIdx.x;
    sp[tid] = pooled[b * 128 + tid];
    __syncthreads();
    float acc = b1[tid];
    #pragma unroll 8
    for (int k = 0; k < 128; k++) acc += sp[k] * w1[k * 128 + tid];
    s1[tid] = leakyf(acc);
    __syncthreads();
    if (tid < 10) {
        float a2 = b2[tid];
        #pragma unroll 8
        for (int k = 0; k < 128; k++) a2 += s1[k] * w2[k * 10 + tid];
        s2[tid] = leakyf(a2);
    }
    __syncthreads();
    if (tid == 0) {
        float mx = -1e30f;
        for (int j = 0; j < 10; j++) mx = fmaxf(mx, s2[j]);
        float ex[10], sum = 0.f;
        for (int j = 0; j < 10; j++) { ex[j] = expf(s2[j] - mx); sum += ex[j]; }
        float inv = 1.f / sum;
        for (int j = 0; j < 10; j++) out[b * 10 + j] = ex[j] * inv;
    }
}

// ---------------------------------------------------------------------------
// Node score: out[(r%64)*Nper + r/64] = sigmoid(nh2[r] . n_w3 + b3)
// ---------------------------------------------------------------------------
__global__ void score_kernel(const float* __restrict__ nh, const float* __restrict__ w3,
                             const float* __restrict__ b3, float* __restrict__ out,
                             int N, int Nper)
{
    int r = blockIdx.x * 8 + (threadIdx.x >> 5);
    int lane = threadIdx.x & 31;
    if (r >= N) return;
    float4 v = *(const float4*)(nh + (size_t)r * HD + lane * 4);
    float4 w = *(const float4*)(w3 + lane * 4);
    float acc = v.x * w.x + v.y * w.y + v.z * w.z + v.w * w.w;
    #pragma unroll
    for (int o = 16; o; o >>= 1) acc += __shfl_xor_sync(0xffffffffu, acc, o);
    if (lane == 0) {
        float z = acc + b3[0];
        out[(size_t)(r & 63) * Nper + (r >> 6)] = 1.f / (1.f + expf(-z));
    }
}

// ---------------------------------------------------------------------------
extern "C" void kernel_launch(void* const* d_in, const int* in_sizes, int n_in,
                              void* d_out, int out_size)
{
    const float* x     = (const float*)d_in[0];
    const int*   ei    = (const int*)  d_in[1];
    const float* ea    = (const float*)d_in[2];
    const float* e1_w  = (const float*)d_in[3];
    const float* e1_b  = (const float*)d_in[4];
    const float* c1_w1 = (const float*)d_in[5];
    const float* c1_b1 = (const float*)d_in[6];
    const float* c1_w2 = (const float*)d_in[7];
    const float* c1_b2 = (const float*)d_in[8];
    const float* e2_w  = (const float*)d_in[9];
    const float* e2_b  = (const float*)d_in[10];
    const float* c2_w1 = (const float*)d_in[11];
    const float* c2_b1 = (const float*)d_in[12];
    const float* c2_w2 = (const float*)d_in[13];
    const float* c2_b2 = (const float*)d_in[14];
    const float* a_w1  = (const float*)d_in[15];
    const float* a_b1  = (const float*)d_in[16];
    const float* a_w2  = (const float*)d_in[17];
    const float* a_b2  = (const float*)d_in[18];
    const float* n_w1  = (const float*)d_in[19];
    const float* n_b1  = (const float*)d_in[20];
    const float* n_w2  = (const float*)d_in[21];
    const float* n_b2  = (const float*)d_in[22];
    const float* n_w3  = (const float*)d_in[23];
    const float* n_b3  = (const float*)d_in[24];

    int N = in_sizes[0] / 32;
    int E = in_sizes[1] / 2;
    int Nper = N / 64;
    const int* src = ei;
    const int* dst = ei + E;

    float *agg1, *h, *agg2, *h2, *t1, *pooled;
    cudaGetSymbolAddress((void**)&agg1,   g_agg1);
    cudaGetSymbolAddress((void**)&h,      g_h);
    cudaGetSymbolAddress((void**)&agg2,   g_agg2);
    cudaGetSymbolAddress((void**)&h2,     g_h2);
    cudaGetSymbolAddress((void**)&t1,     g_t1);
    cudaGetSymbolAddress((void**)&pooled, g_pooled);

    float* out = (float*)d_out;

    cudaMemsetAsync(agg1, 0, (size_t)N * 32 * sizeof(float));
    cudaMemsetAsync(agg2, 0, (size_t)N * HD * sizeof(float));

    // GINE layer 1
    edge1_kernel<<<(E / E1_CHUNK + 7) / 8, 256>>>(x, src, dst, ea, e1_w, e1_b, agg1, E);
    gemm_kernel<32, 0, true ><<<N / 64, 256>>>(x,  agg1, c1_w1, c1_b1, t1);
    gemm_kernel<128, 1, false><<<N / 64, 256>>>(t1, t1,   c1_w2, c1_b2, h);   // relu(leaky(z)) == relu(z)

    // GINE layer 2 (launch index 5 -> ncu captures this kernel)
    edge2_kernel<<<(E / E2_CHUNK + 7) / 8, 256>>>(h, src, dst, ea, e2_w, e2_b, agg2, E);
    gemm_kernel<128, 0, true ><<<N / 64, 256>>>(h,  agg2, c2_w1, c2_b1, t1);
    gemm_kernel<128, 0, false><<<N / 64, 256>>>(t1, t1,   c2_w2, c2_b2, h2);

    // Action head
    pool_kernel<<<64, 256>>>(h2, pooled, Nper);
    action_kernel<<<64, 128>>>(pooled, a_w1, a_b1, a_w2, a_b2, out);

    // Node score head (reuse agg2 as nh2 buffer)
    gemm_kernel<128, 0, false><<<N / 64, 256>>>(h2, h2, n_w1, n_b1, t1);
    gemm_kernel<128, 0, false><<<N / 64, 256>>>(t1, t1, n_w2, n_b2, agg2);
    score_kernel<<<(N + 7) / 8, 256>>>(agg2, n_w3, n_b3, out + 640, N, Nper);
}

// round 6
// speedup vs baseline: 1.1126x; 1.1126x over previous
#include <cuda_runtime.h>
#include <math.h>

#define NMAX 65536
#define HD   128

typedef unsigned long long u64;

// Scratch (device globals: no allocation allowed in kernel_launch)
__device__ float g_agg1[NMAX * 32];
__device__ float g_h   [NMAX * HD];
__device__ float g_agg2[NMAX * HD];   // reused as nh2 buffer at the end
__device__ float g_h2  [NMAX * HD];
__device__ float g_t1  [NMAX * HD];
__device__ float g_pooled[64 * HD];

__device__ __forceinline__ float leakyf(float v) { return v > 0.f ? v : 0.01f * v; }

__device__ __forceinline__ u64 pack2(float lo, float hi) {
    u64 r; asm("mov.b64 %0, {%1, %2};" : "=l"(r) : "f"(lo), "f"(hi)); return r;
}
__device__ __forceinline__ void unpack2(float& lo, float& hi, u64 v) {
    asm("mov.b64 {%0, %1}, %2;" : "=f"(lo), "=f"(hi) : "l"(v));
}
__device__ __forceinline__ u64 fma2(u64 a, u64 b, u64 c) {
    u64 d; asm("fma.rn.f32x2 %0, %1, %2, %3;" : "=l"(d) : "l"(a), "l"(b), "l"(c)); return d;
}

// ---------------------------------------------------------------------------
// Edge layer 1: msg = relu(x[src] + ea @ e1_w + b); red-add into agg1 [N,32]
// One warp / 32 edges; lane owns 1 of 32 channels. W in regs. (R3 version)
// ---------------------------------------------------------------------------
#define E1_CHUNK 32
__global__ __launch_bounds__(256)
void edge1_kernel(const float* __restrict__ x, const int* __restrict__ src,
                  const int* __restrict__ dst, const float* __restrict__ ea,
                  const float* __restrict__ W, const float* __restrict__ bias,
                  float* __restrict__ agg, int E)
{
    int lane = threadIdx.x & 31;
    int warp = blockIdx.x * 8 + (threadIdx.x >> 5);
    int base = warp * E1_CHUNK;
    if (base >= E) return;

    float w[16];
    #pragma unroll
    for (int k = 0; k < 16; k++) w[k] = __ldg(&W[k * 32 + lane]);
    float b = __ldg(&bias[lane]);

    int sA = __ldg(&src[base + lane]);
    int sD = __ldg(&dst[base + lane]);

    #pragma unroll 4
    for (int i = 0; i < E1_CHUNK; i++) {
        int e = base + i;
        int s = __shfl_sync(0xffffffffu, sA, i);
        int d = __shfl_sync(0xffffffffu, sD, i);
        float av = (lane < 16) ? __ldg(&ea[(size_t)e * 16 + lane]) : 0.f;
        float g = __ldg(&x[(size_t)s * 32 + lane]);
        float t = b;
        #pragma unroll
        for (int k = 0; k < 16; k++)
            t = fmaf(__shfl_sync(0xffffffffu, av, k), w[k], t);
        float m = fmaxf(t + g, 0.f);
        asm volatile("red.global.add.f32 [%0], %1;"
                     :: "l"(agg + (size_t)d * 32 + lane), "f"(m) : "memory");
    }
}

// ---------------------------------------------------------------------------
// Edge layer 2: msg = relu(h[src] + ea @ e2_w + b); red-add into agg2 [N,128]
// TWO warps per 16-edge chunk; each warp owns 64 channels (lane = 2 ch).
// W per lane: 16 u64 = 32 regs -> 4 CTAs/SM occupancy.
// ---------------------------------------------------------------------------
#define E2_CHUNK 16
__global__ __launch_bounds__(256, 4)
void edge2_kernel(const float* __restrict__ h, const int* __restrict__ src,
                  const int* __restrict__ dst, const float* __restrict__ ea,
                  const float* __restrict__ W, const float* __restrict__ bias,
                  float* __restrict__ agg, int E)
{
    int lane = threadIdx.x & 31;
    int warp = blockIdx.x * 8 + (threadIdx.x >> 5);
    int chunk = warp >> 1;
    int half  = warp & 1;
    int base = chunk * E2_CHUNK;
    if (base >= E) return;
    int ch = half * 64 + lane * 2;

    u64 w2[16];
    #pragma unroll
    for (int k = 0; k < 16; k++) {
        float2 wv = *(const float2*)(W + (size_t)k * 128 + ch);
        w2[k] = pack2(wv.x, wv.y);
    }
    float2 bv = *(const float2*)(bias + ch);
    u64 b2 = pack2(bv.x, bv.y);

    // lanes 0..15 hold src indices of the chunk, lanes 16..31 hold dst indices
    int li = lane & 15;
    int sd = (lane < 16) ? __ldg(&src[base + li]) : __ldg(&dst[base + li]);

    for (int i = 0; i < E2_CHUNK; i++) {
        int e = base + i;
        int s = __shfl_sync(0xffffffffu, sd, i);
        int d = __shfl_sync(0xffffffffu, sd, 16 + i);
        float av = (lane < 16) ? __ldg(&ea[(size_t)e * 16 + lane]) : 0.f;
        float2 g = *(const float2*)(h + (size_t)s * HD + ch);

        u64 tE = b2, tO = 0ull;   // even-k / odd-k chains
        #pragma unroll
        for (int k = 0; k < 16; k += 2) {
            float a0 = __shfl_sync(0xffffffffu, av, k);
            float a1 = __shfl_sync(0xffffffffu, av, k + 1);
            tE = fma2(pack2(a0, a0), w2[k],     tE);
            tO = fma2(pack2(a1, a1), w2[k + 1], tO);
        }
        float tx, ty, ux, uy;
        unpack2(tx, ty, tE);
        unpack2(ux, uy, tO);
        float mx = fmaxf(tx + ux + g.x, 0.f);
        float my = fmaxf(ty + uy + g.y, 0.f);
        asm volatile("red.global.add.v2.f32 [%0], {%1,%2};"
                     :: "l"(agg + (size_t)d * HD + ch), "f"(mx), "f"(my) : "memory");
    }
}

// ---------------------------------------------------------------------------
// GEMM: Out[N,128] = act( (In (+In2)) @ W[K,128] + bias )   (R3/R1 version)
// 256 threads/block, 64 rows x 128 cols tile, per-thread 8 rows x 4 cols.
// ACT: 0 = leaky_relu(0.01), 1 = relu
// ---------------------------------------------------------------------------
template<int K, int ACT, bool ADD>
__global__ __launch_bounds__(256)
void gemm_kernel(const float* __restrict__ In, const float* __restrict__ In2,
                 const float* __restrict__ W, const float* __restrict__ bias,
                 float* __restrict__ Out)
{
    __shared__ float sIn[64 * K];
    __shared__ float sW[16 * 128];
    int tid = threadIdx.x;
    int row0 = blockIdx.x * 64;

    const float4* inp  = (const float4*)(In  + (size_t)row0 * K);
    const float4* inp2 = (const float4*)(In2 + (size_t)row0 * K);
    for (int i = tid; i < (64 * K) / 4; i += 256) {
        float4 v = inp[i];
        if (ADD) {
            float4 u = inp2[i];
            v.x += u.x; v.y += u.y; v.z += u.z; v.w += u.w;
        }
        ((float4*)sIn)[i] = v;
    }

    int cx = tid & 31;
    int ry = tid >> 5;
    float4 b4 = ((const float4*)bias)[cx];
    float4 acc[8];
    #pragma unroll
    for (int m = 0; m < 8; m++) acc[m] = b4;

    for (int kc = 0; kc < K; kc += 16) {
        __syncthreads();
        for (int i = tid; i < (16 * 128) / 4; i += 256)
            ((float4*)sW)[i] = ((const float4*)(W + (size_t)kc * 128))[i];
        __syncthreads();
        #pragma unroll
        for (int k = 0; k < 16; k++) {
            float4 w = ((float4*)sW)[k * 32 + cx];
            #pragma unroll
            for (int m = 0; m < 8; m++) {
                float a = sIn[(ry * 8 + m) * K + (kc + k)];
                acc[m].x += a * w.x; acc[m].y += a * w.y;
                acc[m].z += a * w.z; acc[m].w += a * w.w;
            }
        }
    }

    #pragma unroll
    for (int m = 0; m < 8; m++) {
        float4 v = acc[m];
        if (ACT == 0) {
            v.x = leakyf(v.x); v.y = leakyf(v.y); v.z = leakyf(v.z); v.w = leakyf(v.w);
        } else {
            v.x = fmaxf(v.x, 0.f); v.y = fmaxf(v.y, 0.f);
            v.z = fmaxf(v.z, 0.f); v.w = fmaxf(v.w, 0.f);
        }
        *(float4*)(Out + (size_t)(row0 + ry * 8 + m) * 128 + cx * 4) = v;
    }
}

// ---------------------------------------------------------------------------
// Graph mean pooling: pooled[b][c] = mean_i h2[b*Nper+i][c]
// ---------------------------------------------------------------------------
__global__ void pool_kernel(const float* __restrict__ h2, float* __restrict__ pooled, int Nper)
{
    int b = blockIdx.x;
    int tid = threadIdx.x;
    int c = tid & 127, half = tid >> 7;
    float s = 0.f;
    const float* base = h2 + (size_t)b * Nper * HD + c;
    for (int i = half; i < Nper; i += 2) s += base[(size_t)i * HD];
    __shared__ float sm[256];
    sm[tid] = s;
    __syncthreads();
    if (half == 0) pooled[b * HD + c] = (sm[c] + sm[128 + c]) / (float)Nper;
}

// ---------------------------------------------------------------------------
// Action head: softmax(leaky(leaky(pooled@a_w1+b1)@a_w2+b2))
// ---------------------------------------------------------------------------
__global__ void action_kernel(const float* __restrict__ pooled,
                              const float* __restrict__ w1, const float* __restrict__ b1,
                              const float* __restrict__ w2, const float* __restrict__ b2,
                              float* __restrict__ out)
{
    __shared__ float sp[128], s1[128], s2[10];
    int b = blockIdx.x;
    int tid = threadIdx.x;
    sp[tid] = pooled[b * 128 + tid];
    __syncthreads();
    float acc = b1[tid];
    #pragma unroll 8
    for (int k = 0; k < 128; k++) acc += sp[k] * w1[k * 128 + tid];
    s1[tid] = leakyf(acc);
    __syncthreads();
    if (tid < 10) {
        float a2 = b2[tid];
        #pragma unroll 8
        for (int k = 0; k < 128; k++) a2 += s1[k] * w2[k * 10 + tid];
        s2[tid] = leakyf(a2);
    }
    __syncthreads();
    if (tid == 0) {
        float mx = -1e30f;
        for (int j = 0; j < 10; j++) mx = fmaxf(mx, s2[j]);
        float ex[10], sum = 0.f;
        for (int j = 0; j < 10; j++) { ex[j] = expf(s2[j] - mx); sum += ex[j]; }
        float inv = 1.f / sum;
        for (int j = 0; j < 10; j++) out[b * 10 + j] = ex[j] * inv;
    }
}

// ---------------------------------------------------------------------------
// Node score: out[(r%64)*Nper + r/64] = sigmoid(nh2[r] . n_w3 + b3)
// ---------------------------------------------------------------------------
__global__ void score_kernel(const float* __restrict__ nh, const float* __restrict__ w3,
                             const float* __restrict__ b3, float* __restrict__ out,
                             int N, int Nper)
{
    int r = blockIdx.x * 8 + (threadIdx.x >> 5);
    int lane = threadIdx.x & 31;
    if (r >= N) return;
    float4 v = *(const float4*)(nh + (size_t)r * HD + lane * 4);
    float4 w = *(const float4*)(w3 + lane * 4);
    float acc = v.x * w.x + v.y * w.y + v.z * w.z + v.w * w.w;
    #pragma unroll
    for (int o = 16; o; o >>= 1) acc += __shfl_xor_sync(0xffffffffu, acc, o);
    if (lane == 0) {
        float z = acc + b3[0];
        out[(size_t)(r & 63) * Nper + (r >> 6)] = 1.f / (1.f + expf(-z));
    }
}

// ---------------------------------------------------------------------------
extern "C" void kernel_launch(void* const* d_in, const int* in_sizes, int n_in,
                              void* d_out, int out_size)
{
    const float* x     = (const float*)d_in[0];
    const int*   ei    = (const int*)  d_in[1];
    const float* ea    = (const float*)d_in[2];
    const float* e1_w  = (const float*)d_in[3];
    const float* e1_b  = (const float*)d_in[4];
    const float* c1_w1 = (const float*)d_in[5];
    const float* c1_b1 = (const float*)d_in[6];
    const float* c1_w2 = (const float*)d_in[7];
    const float* c1_b2 = (const float*)d_in[8];
    const float* e2_w  = (const float*)d_in[9];
    const float* e2_b  = (const float*)d_in[10];
    const float* c2_w1 = (const float*)d_in[11];
    const float* c2_b1 = (const float*)d_in[12];
    const float* c2_w2 = (const float*)d_in[13];
    const float* c2_b2 = (const float*)d_in[14];
    const float* a_w1  = (const float*)d_in[15];
    const float* a_b1  = (const float*)d_in[16];
    const float* a_w2  = (const float*)d_in[17];
    const float* a_b2  = (const float*)d_in[18];
    const float* n_w1  = (const float*)d_in[19];
    const float* n_b1  = (const float*)d_in[20];
    const float* n_w2  = (const float*)d_in[21];
    const float* n_b2  = (const float*)d_in[22];
    const float* n_w3  = (const float*)d_in[23];
    const float* n_b3  = (const float*)d_in[24];

    int N = in_sizes[0] / 32;
    int E = in_sizes[1] / 2;
    int Nper = N / 64;
    const int* src = ei;
    const int* dst = ei + E;

    float *agg1, *h, *agg2, *h2, *t1, *pooled;
    cudaGetSymbolAddress((void**)&agg1,   g_agg1);
    cudaGetSymbolAddress((void**)&h,      g_h);
    cudaGetSymbolAddress((void**)&agg2,   g_agg2);
    cudaGetSymbolAddress((void**)&h2,     g_h2);
    cudaGetSymbolAddress((void**)&t1,     g_t1);
    cudaGetSymbolAddress((void**)&pooled, g_pooled);

    float* out = (float*)d_out;

    cudaMemsetAsync(agg1, 0, (size_t)N * 32 * sizeof(float));
    cudaMemsetAsync(agg2, 0, (size_t)N * HD * sizeof(float));

    // GINE layer 1
    edge1_kernel<<<(E / E1_CHUNK + 7) / 8, 256>>>(x, src, dst, ea, e1_w, e1_b, agg1, E);
    gemm_kernel<32, 0, true ><<<N / 64, 256>>>(x,  agg1, c1_w1, c1_b1, t1);
    gemm_kernel<128, 1, false><<<N / 64, 256>>>(t1, t1,   c1_w2, c1_b2, h);   // relu(leaky(z)) == relu(z)

    // GINE layer 2 (launch index 5 -> ncu captures this kernel)
    edge2_kernel<<<(2 * (E / E2_CHUNK) + 7) / 8, 256>>>(h, src, dst, ea, e2_w, e2_b, agg2, E);
    gemm_kernel<128, 0, true ><<<N / 64, 256>>>(h,  agg2, c2_w1, c2_b1, t1);
    gemm_kernel<128, 0, false><<<N / 64, 256>>>(t1, t1,   c2_w2, c2_b2, h2);

    // Action head
    pool_kernel<<<64, 256>>>(h2, pooled, Nper);
    action_kernel<<<64, 128>>>(pooled, a_w1, a_b1, a_w2, a_b2, out);

    // Node score head (reuse agg2 as nh2 buffer)
    gemm_kernel<128, 0, false><<<N / 64, 256>>>(h2, h2, n_w1, n_b1, t1);
    gemm_kernel<128, 0, false><<<N / 64, 256>>>(t1, t1, n_w2, n_b2, agg2);
    score_kernel<<<(N + 7) / 8, 256>>>(agg2, n_w3, n_b3, out + 640, N, Nper);
}